// round 11
// baseline (speedup 1.0000x reference)
#include <cuda_runtime.h>
#include <math.h>
#include <stdint.h>

#define S_TOK 257
#define D_DIM 1024
#define HID 4096
#define NLAYER 12
#define NC 256
#define CSZ 128
#define AGE_V 258
#define OBS_N 2048
#define OUT_N 512
#define HEADS 16
#define DH 64

// ---------------- scratch (device globals; no allocation allowed) ----------
__device__ float g_x[S_TOK * D_DIM];
__device__ float g_q[S_TOK * D_DIM];
__device__ float g_k[S_TOK * D_DIM];
__device__ float g_v[S_TOK * D_DIM];
__device__ float g_ao[S_TOK * D_DIM];
__device__ float g_ffn[S_TOK * HID];
__device__ float g_part[4 * S_TOK * D_DIM];   // split-K partials (KS<=4)

// ---------------- helpers ---------------------------------------------------
__device__ __forceinline__ float warpMax(float v) {
#pragma unroll
    for (int o = 16; o; o >>= 1) v = fmaxf(v, __shfl_xor_sync(0xffffffffu, v, o));
    return v;
}
__device__ __forceinline__ float warpSum(float v) {
#pragma unroll
    for (int o = 16; o; o >>= 1) v += __shfl_xor_sync(0xffffffffu, v, o);
    return v;
}
__device__ __forceinline__ uint32_t pkh2(float a, float b) {   // lo=a, hi=b
    uint32_t r;
    asm("cvt.rn.f16x2.f32 %0, %1, %2;" : "=r"(r) : "f"(b), "f"(a));
    return r;
}
__device__ __forceinline__ uint32_t smem_u32p(const void* p) {
    uint32_t a;
    asm("{ .reg .u64 t; cvta.to.shared.u64 t, %1; cvt.u32.u64 %0, t; }" : "=r"(a) : "l"(p));
    return a;
}
__device__ __forceinline__ void mma16816(float (&d)[4], const uint32_t (&a)[4], const uint32_t (&b)[2]) {
    asm volatile(
        "mma.sync.aligned.m16n8k16.row.col.f32.f16.f16.f32 "
        "{%0,%1,%2,%3}, {%4,%5,%6,%7}, {%8,%9}, {%0,%1,%2,%3};\n"
        : "+f"(d[0]), "+f"(d[1]), "+f"(d[2]), "+f"(d[3])
        : "r"(a[0]), "r"(a[1]), "r"(a[2]), "r"(a[3]), "r"(b[0]), "r"(b[1]));
}
__device__ __forceinline__ void ldsm4(uint32_t& r0, uint32_t& r1, uint32_t& r2, uint32_t& r3,
                                      uint32_t addr) {
    asm volatile("ldmatrix.sync.aligned.m8n8.x4.shared.b16 {%0,%1,%2,%3}, [%4];"
                 : "=r"(r0), "=r"(r1), "=r"(r2), "=r"(r3) : "r"(addr));
}

// ============================================================================
// fp16 GEMM core, ldmatrix + DOUBLE-BUFFERED smem (one barrier per k-tile).
// Block 128x64, BK=32, 256 threads (8 warps 4x2, warp tile 32x32).
// ============================================================================
#define ROWW 20
#define A_U32 (128 * ROWW)          // u32 per A buffer
#define B_U32 (64 * ROWW)
#define A_BYTES (A_U32 * 4)
#define B_BYTES (B_U32 * 4)

__device__ __forceinline__ void f16_core128(
    const float* __restrict__ A, const float* __restrict__ B,
    int K, int bm, int bn, int kbeg, int ktiles,
    float (&acc)[2][4][4], uint32_t* __restrict__ As, uint32_t* __restrict__ Bs)
{
    const int tid = threadIdx.x;
    const int lane = tid & 31, wid = tid >> 5;
    const int wm = wid & 3, wn = wid >> 2;
    const int sub = lane >> 3, r8 = lane & 7;

    const uint32_t As_b = smem_u32p(As);
    const uint32_t Bs_b = smem_u32p(Bs);
    uint32_t a_addr[2];
#pragma unroll
    for (int mi = 0; mi < 2; mi++) {
        const int row = wm * 32 + mi * 16 + (sub & 1) * 8 + r8;
        a_addr[mi] = As_b + (row * ROWW + (sub >> 1) * 4) * 4;
    }
    uint32_t b_addr[2];
#pragma unroll
    for (int p = 0; p < 2; p++) {
        const int row = wn * 32 + p * 16 + (sub >> 1) * 8 + r8;
        b_addr[p] = Bs_b + (row * ROWW + (sub & 1) * 4) * 4;
    }

    // loader mapping
    int aoff[4];
    const float* aptr[4];
#pragma unroll
    for (int i = 0; i < 4; i++) {
        const int idx = tid + i * 256;
        const int row = idx >> 3, f = idx & 7;
        aoff[i] = row * ROWW + f * 2;
        aptr[i] = A + (size_t)(bm + row) * K + kbeg + f * 4;
    }
    int boff[2];
    const float* bptr[2];
#pragma unroll
    for (int i = 0; i < 2; i++) {
        const int idx = tid + i * 256;
        const int row = idx >> 3, f = idx & 7;
        boff[i] = row * ROWW + f * 2;
        bptr[i] = B + (size_t)(bn + row) * K + kbeg + f * 4;
    }

    float4 pa[4], pb[2];
#pragma unroll
    for (int i = 0; i < 4; i++) pa[i] = *(const float4*)(aptr[i]);
#pragma unroll
    for (int i = 0; i < 2; i++) pb[i] = *(const float4*)(bptr[i]);
#pragma unroll
    for (int i = 0; i < 4; i++)
        *(uint2*)&As[aoff[i]] = make_uint2(pkh2(pa[i].x, pa[i].y), pkh2(pa[i].z, pa[i].w));
#pragma unroll
    for (int i = 0; i < 2; i++)
        *(uint2*)&Bs[boff[i]] = make_uint2(pkh2(pb[i].x, pb[i].y), pkh2(pb[i].z, pb[i].w));
    __syncthreads();

    int buf = 0;
    for (int kt = 0; kt < ktiles; kt++) {
        const bool has_next = (kt + 1 < ktiles);
        if (has_next) {
            const int off = (kt + 1) * 32;
#pragma unroll
            for (int i = 0; i < 4; i++) pa[i] = *(const float4*)(aptr[i] + off);
#pragma unroll
            for (int i = 0; i < 2; i++) pb[i] = *(const float4*)(bptr[i] + off);
        }
        const uint32_t a_bo = buf ? A_BYTES : 0;
        const uint32_t b_bo = buf ? B_BYTES : 0;
#pragma unroll
        for (int ks = 0; ks < 2; ks++) {           // two k16 steps per 32-K tile
            const uint32_t koff = ks * 8 * 4;
            uint32_t af[2][4], bq[2][4];
#pragma unroll
            for (int mi = 0; mi < 2; mi++)
                ldsm4(af[mi][0], af[mi][1], af[mi][2], af[mi][3], a_addr[mi] + a_bo + koff);
#pragma unroll
            for (int p = 0; p < 2; p++)
                ldsm4(bq[p][0], bq[p][1], bq[p][2], bq[p][3], b_addr[p] + b_bo + koff);
#pragma unroll
            for (int mi = 0; mi < 2; mi++) {
#pragma unroll
                for (int p = 0; p < 2; p++) {
                    const uint32_t b0[2] = {bq[p][0], bq[p][1]};
                    const uint32_t b1[2] = {bq[p][2], bq[p][3]};
                    mma16816(acc[mi][p * 2 + 0], af[mi], b0);
                    mma16816(acc[mi][p * 2 + 1], af[mi], b1);
                }
            }
        }
        if (has_next) {
            const int nb = buf ^ 1;
            uint32_t* An = As + (nb ? A_U32 : 0);
            uint32_t* Bn = Bs + (nb ? B_U32 : 0);
#pragma unroll
            for (int i = 0; i < 4; i++)
                *(uint2*)&An[aoff[i]] = make_uint2(pkh2(pa[i].x, pa[i].y), pkh2(pa[i].z, pa[i].w));
#pragma unroll
            for (int i = 0; i < 2; i++)
                *(uint2*)&Bn[boff[i]] = make_uint2(pkh2(pb[i].x, pb[i].y), pkh2(pb[i].z, pb[i].w));
            __syncthreads();
            buf = nb;
        }
    }
}

#define EPI128_VARS \
    const int lane = threadIdx.x & 31, wid = threadIdx.x >> 5; \
    const int wm = wid & 3, wn = wid >> 2; \
    const int fr = lane >> 2, fc = lane & 3;

// ---- slim path: compute single row (row 256) as fp32 matvec -----------------
__device__ __forceinline__ void slim_row(
    const float* __restrict__ Arow, const float* __restrict__ B,
    int K, int bn, int kbeg, int klen,
    float* xs, float* outvals, int* outcols)
{
    const int tid = threadIdx.x;
    const int wid = tid >> 5, lane = tid & 31;
    const int k4 = klen >> 2;
    for (int i = tid; i < k4; i += 256)
        ((float4*)xs)[i] = ((const float4*)Arow)[i];
    __syncthreads();
#pragma unroll
    for (int cc = 0; cc < 8; cc++) {
        const int col = bn + wid * 8 + cc;
        const float4* wr = (const float4*)(B + (size_t)col * K + kbeg);
        float s = 0.f;
        for (int kb = lane; kb < k4; kb += 32) {
            const float4 w = wr[kb], xv = ((const float4*)xs)[kb];
            s += w.x * xv.x + w.y * xv.y + w.z * xv.z + w.w * xv.w;
        }
        s = warpSum(s);
        outvals[cc] = s;
        outcols[cc] = col;
    }
}

// ---- fused QKV ---------------------------------------------------------------
__global__ __launch_bounds__(256) void gemm_qkv_kernel(
    const float* __restrict__ A,
    const float* __restrict__ Wq_, const float* __restrict__ Wk_, const float* __restrict__ Wv_,
    const float* __restrict__ bq_, const float* __restrict__ bk_, const float* __restrict__ bv_,
    float* __restrict__ Q, float* __restrict__ Ko, float* __restrict__ V,
    int M, int N, int K)
{
    __shared__ uint32_t As[2 * A_U32];
    __shared__ uint32_t Bs[2 * B_U32];
    const int z = blockIdx.z;
    const float* B    = (z == 0) ? Wq_ : (z == 1) ? Wk_ : Wv_;
    const float* bias = (z == 0) ? bq_ : (z == 1) ? bk_ : bv_;
    float* C          = (z == 0) ? Q   : (z == 1) ? Ko  : V;
    const int bn = blockIdx.x * 64;

    if (blockIdx.y == 2) {   // slim: row 256 only
        float vals[8]; int cols[8];
        slim_row(A + (size_t)256 * K, B, K, bn, 0, K, (float*)As, vals, cols);
        if ((threadIdx.x & 31) == 0) {
#pragma unroll
            for (int cc = 0; cc < 8; cc++)
                C[(size_t)256 * N + cols[cc]] = vals[cc] + bias[cols[cc]];
        }
        return;
    }

    const int bm = blockIdx.y * 128;
    float acc[2][4][4] = {};
    f16_core128(A, B, K, bm, bn, 0, K / 32, acc, As, Bs);

    EPI128_VARS
#pragma unroll
    for (int mi = 0; mi < 2; mi++)
#pragma unroll
        for (int ni = 0; ni < 4; ni++) {
            const int r = bm + wm * 32 + mi * 16 + fr;
            const int c = bn + wn * 32 + ni * 8 + fc * 2;
            const float bx = bias[c], by = bias[c + 1];
            float2 o0 = {acc[mi][ni][0] + bx, acc[mi][ni][1] + by};
            float2 o1 = {acc[mi][ni][2] + bx, acc[mi][ni][3] + by};
            *(float2*)(C + (size_t)r * N + c) = o0;
            *(float2*)(C + (size_t)(r + 8) * N + c) = o1;
        }
}

// ---- direct GEMM with bias (+relu) -------------------------------------------
__global__ __launch_bounds__(256) void gemm_direct_kernel(
    const float* __restrict__ A, const float* __restrict__ B,
    const float* __restrict__ bias, float* __restrict__ C,
    int M, int N, int K, int relu_flag)
{
    __shared__ uint32_t As[2 * A_U32];
    __shared__ uint32_t Bs[2 * B_U32];
    const int bn = blockIdx.x * 64;

    if (blockIdx.y == 2) {
        float vals[8]; int cols[8];
        slim_row(A + (size_t)256 * K, B, K, bn, 0, K, (float*)As, vals, cols);
        if ((threadIdx.x & 31) == 0) {
#pragma unroll
            for (int cc = 0; cc < 8; cc++) {
                float s = vals[cc] + bias[cols[cc]];
                if (relu_flag) s = fmaxf(s, 0.f);
                C[(size_t)256 * N + cols[cc]] = s;
            }
        }
        return;
    }

    const int bm = blockIdx.y * 128;
    float acc[2][4][4] = {};
    f16_core128(A, B, K, bm, bn, 0, K / 32, acc, As, Bs);

    EPI128_VARS
#pragma unroll
    for (int mi = 0; mi < 2; mi++)
#pragma unroll
        for (int ni = 0; ni < 4; ni++) {
            const int r = bm + wm * 32 + mi * 16 + fr;
            const int c = bn + wn * 32 + ni * 8 + fc * 2;
            const float bx = bias[c], by = bias[c + 1];
            float2 o0 = {acc[mi][ni][0] + bx, acc[mi][ni][1] + by};
            float2 o1 = {acc[mi][ni][2] + bx, acc[mi][ni][3] + by};
            if (relu_flag) {
                o0.x = fmaxf(o0.x, 0.f); o0.y = fmaxf(o0.y, 0.f);
                o1.x = fmaxf(o1.x, 0.f); o1.y = fmaxf(o1.y, 0.f);
            }
            *(float2*)(C + (size_t)r * N + c) = o0;
            *(float2*)(C + (size_t)(r + 8) * N + c) = o1;
        }
}

// ---- split-K GEMM (raw partials) ---------------------------------------------
__global__ __launch_bounds__(256) void gemm_splitk_kernel(
    const float* __restrict__ A, const float* __restrict__ B,
    float* __restrict__ part, int M, int N, int K, int klen)
{
    __shared__ uint32_t As[2 * A_U32];
    __shared__ uint32_t Bs[2 * B_U32];
    const int bn = blockIdx.x * 64;
    const int z = blockIdx.z;
    float* C = part + (size_t)z * M * N;

    if (blockIdx.y == 2) {
        float vals[8]; int cols[8];
        slim_row(A + (size_t)256 * K + z * klen, B, K, bn, z * klen, klen, (float*)As, vals, cols);
        if ((threadIdx.x & 31) == 0) {
#pragma unroll
            for (int cc = 0; cc < 8; cc++)
                C[(size_t)256 * N + cols[cc]] = vals[cc];
        }
        return;
    }

    const int bm = blockIdx.y * 128;
    float acc[2][4][4] = {};
    f16_core128(A, B, K, bm, bn, z * klen, klen / 32, acc, As, Bs);

    EPI128_VARS
#pragma unroll
    for (int mi = 0; mi < 2; mi++)
#pragma unroll
        for (int ni = 0; ni < 4; ni++) {
            const int r = bm + wm * 32 + mi * 16 + fr;
            const int c = bn + wn * 32 + ni * 8 + fc * 2;
            float2 o0 = {acc[mi][ni][0], acc[mi][ni][1]};
            float2 o1 = {acc[mi][ni][2], acc[mi][ni][3]};
            *(float2*)(C + (size_t)r * N + c) = o0;
            *(float2*)(C + (size_t)(r + 8) * N + c) = o1;
        }
}

// ---- fused combine(split-K) + bias + residual + LayerNorm --------------------
__global__ __launch_bounds__(256) void combine_ln_kernel(
    const float* __restrict__ part, int KS,
    const float* __restrict__ bias, const float* __restrict__ res,
    const float* __restrict__ g, const float* __restrict__ b,
    float* __restrict__ out, int M)
{
    const int row = blockIdx.x;
    const int tid = threadIdx.x;
    const int lane = tid & 31, warp = tid >> 5;
    __shared__ float rs[8], rs2[8];
    __shared__ float smv[2];

    float4 s = ((const float4*)(part + (size_t)row * D_DIM))[tid];
    for (int z = 1; z < KS; z++) {
        const float4 t = ((const float4*)(part + ((size_t)z * M + row) * D_DIM))[tid];
        s.x += t.x; s.y += t.y; s.z += t.z; s.w += t.w;
    }
    const float4 b4 = ((const float4*)bias)[tid];
    s.x += b4.x; s.y += b4.y; s.z += b4.z; s.w += b4.w;
    const float4 r4 = ((const float4*)(res + (size_t)row * D_DIM))[tid];
    s.x += r4.x; s.y += r4.y; s.z += r4.z; s.w += r4.w;

    float sum = s.x + s.y + s.z + s.w;
    float sq = s.x * s.x + s.y * s.y + s.z * s.z + s.w * s.w;
    sum = warpSum(sum); sq = warpSum(sq);
    if (lane == 0) { rs[warp] = sum; rs2[warp] = sq; }
    __syncthreads();
    if (warp == 0) {
        float t = (lane < 8) ? rs[lane] : 0.f;
        float t2 = (lane < 8) ? rs2[lane] : 0.f;
        t = warpSum(t); t2 = warpSum(t2);
        if (lane == 0) {
            const float mean = t * (1.0f / D_DIM);
            const float var = t2 * (1.0f / D_DIM) - mean * mean;
            smv[0] = mean;
            smv[1] = rsqrtf(var + 1e-5f);
        }
    }
    __syncthreads();
    const float mean = smv[0], inv = smv[1];
    const float4 g4 = ((const float4*)g)[tid];
    const float4 be4 = ((const float4*)b)[tid];
    float4 o;
    o.x = (s.x - mean) * inv * g4.x + be4.x;
    o.y = (s.y - mean) * inv * g4.y + be4.y;
    o.z = (s.z - mean) * inv * g4.z + be4.z;
    o.w = (s.w - mean) * inv * g4.w + be4.w;
    ((float4*)(out + (size_t)row * D_DIM))[tid] = o;
}

// ---------------- attention: block per (head, 16-query tile) ----------------
#define QT 16
__global__ __launch_bounds__(256) void attn3_kernel(
    const float* __restrict__ q, const float* __restrict__ k,
    const float* __restrict__ v, float* __restrict__ o)
{
    const int h = blockIdx.x;
    const int qt = blockIdx.y * QT;
    const int tid = threadIdx.x, lane = tid & 31, warp = tid >> 5;

    __shared__ float Qs[QT][68];
    __shared__ float T[64][68];
    __shared__ float sc[QT][261];
    __shared__ float inv_s[QT];

    const int nq = min(QT, S_TOK - qt);

    {
        const int r = tid >> 4, c4 = (tid & 15) << 2;
        float4 val = (r < nq) ? *(const float4*)(q + (size_t)(qt + r) * D_DIM + h * DH + c4)
                              : make_float4(0.f, 0.f, 0.f, 0.f);
        *(float4*)&Qs[r][c4] = val;
    }

    const int qrow = tid & 15, jg = tid >> 4;

    for (int j0 = 0; j0 < S_TOK; j0 += 64) {
        const int jn = min(64, S_TOK - j0);
        __syncthreads();
#pragma unroll
        for (int i = 0; i < 4; i++) {
            const int idx = tid + i * 256;
            const int r = idx >> 4, c4 = (idx & 15) << 2;
            float4 val = (r < jn) ? *(const float4*)(k + (size_t)(j0 + r) * D_DIM + h * DH + c4)
                                  : make_float4(0.f, 0.f, 0.f, 0.f);
            *(float4*)&T[r][c4] = val;
        }
        __syncthreads();
        for (int jj = jg; jj < jn; jj += 16) {
            const float4* qr4 = (const float4*)Qs[qrow];
            const float4* kr4 = (const float4*)T[jj];
            float s = 0.f;
#pragma unroll
            for (int t = 0; t < 16; t++) {
                const float4 a = qr4[t], bb = kr4[t];
                s += a.x * bb.x + a.y * bb.y + a.z * bb.z + a.w * bb.w;
            }
            sc[qrow][j0 + jj] = s * 0.125f;
        }
    }
    __syncthreads();

#pragma unroll
    for (int ri = 0; ri < 2; ri++) {
        const int r = warp * 2 + ri;
        if (r < nq) {
            float m = -1e30f;
            for (int j = lane; j < S_TOK; j += 32) m = fmaxf(m, sc[r][j]);
            m = warpMax(m);
            float ssum = 0.f;
            for (int j = lane; j < S_TOK; j += 32) {
                const float e = __expf(sc[r][j] - m);
                sc[r][j] = e;
                ssum += e;
            }
            ssum = warpSum(ssum);
            if (lane == 0) inv_s[r] = 1.0f / ssum;
        }
    }
    __syncthreads();

    const int db = (tid >> 4) << 2;
    float4 acc = make_float4(0.f, 0.f, 0.f, 0.f);
    for (int j0 = 0; j0 < S_TOK; j0 += 64) {
        const int jn = min(64, S_TOK - j0);
        __syncthreads();
#pragma unroll
        for (int i = 0; i < 4; i++) {
            const int idx = tid + i * 256;
            const int r = idx >> 4, c4 = (idx & 15) << 2;
            float4 val = (r < jn) ? *(const float4*)(v + (size_t)(j0 + r) * D_DIM + h * DH + c4)
                                  : make_float4(0.f, 0.f, 0.f, 0.f);
            *(float4*)&T[r][c4] = val;
        }
        __syncthreads();
        for (int jj = 0; jj < jn; jj++) {
            const float w = sc[qrow][j0 + jj];
            const float4 vv = *(const float4*)&T[jj][db];
            acc.x += w * vv.x; acc.y += w * vv.y; acc.z += w * vv.z; acc.w += w * vv.w;
        }
    }
    if (qrow < nq) {
        const float iv = inv_s[qrow];
        float4 oo = {acc.x * iv, acc.y * iv, acc.z * iv, acc.w * iv};
        *(float4*)(o + (size_t)(qt + qrow) * D_DIM + h * DH + db) = oo;
    }
}

// ---------------- matvec (embeddings) ---------------------------------------
__global__ __launch_bounds__(256) void matvec_kernel(
    const float* __restrict__ W, const float* __restrict__ bias,
    const float* __restrict__ x, float* __restrict__ out,
    int N, int K, int act)
{
    __shared__ float xs[OBS_N];
    const int tid = threadIdx.x;
    for (int i = tid; i < K; i += 256) xs[i] = x[i];
    __syncthreads();
    const int warp = tid >> 5, lane = tid & 31;
    const int n = blockIdx.x * 8 + warp;
    if (n >= N) return;
    const float4* wr = reinterpret_cast<const float4*>(W + (size_t)n * K);
    const float4* x4 = reinterpret_cast<const float4*>(xs);
    float s = 0.f;
    const int K4 = K >> 2;
    for (int kb = lane; kb < K4; kb += 32) {
        const float4 w = wr[kb], xv = x4[kb];
        s += w.x * xv.x + w.y * xv.y + w.z * xv.z + w.w * xv.w;
    }
    s = warpSum(s);
    if (lane == 0) {
        s += bias[n];
        if (act == 1) s = fmaxf(s, 0.f);
        else if (act == 2) s = tanhf(s);
        out[n] = s;
    }
}

// ---------------- fused output heads (W_out relu | W_concept tanh) ----------
__global__ __launch_bounds__(256) void heads_kernel(
    const float* __restrict__ W_out, const float* __restrict__ b_out,
    const float* __restrict__ W_con, const float* __restrict__ b_con,
    const float* __restrict__ x, float* __restrict__ out)
{
    __shared__ float xs[D_DIM];
    const int tid = threadIdx.x;
    for (int i = tid; i < D_DIM; i += 256) xs[i] = x[i];
    __syncthreads();
    const int warp = tid >> 5, lane = tid & 31;
    const int n = blockIdx.x * 8 + warp;   // 0..639
    const bool is_out = (n < OUT_N);
    const int nn = is_out ? n : n - OUT_N;
    const float* W = is_out ? W_out : W_con;
    const float4* wr = reinterpret_cast<const float4*>(W + (size_t)nn * D_DIM);
    const float4* x4 = reinterpret_cast<const float4*>(xs);
    float s = 0.f;
#pragma unroll 4
    for (int kb = lane; kb < D_DIM / 4; kb += 32) {
        const float4 w = wr[kb], xv = x4[kb];
        s += w.x * xv.x + w.y * xv.y + w.z * xv.z + w.w * xv.w;
    }
    s = warpSum(s);
    if (lane == 0) {
        if (is_out) out[n] = fmaxf(s + b_out[nn], 0.f);
        else        out[n] = tanhf(s + b_con[nn]);
    }
}

// ---------------- concept embedding (rows 1..256 of x) ---------------------
__global__ __launch_bounds__(256) void cemb_kernel(
    const float* __restrict__ concepts, const float* __restrict__ Wc,
    const float* __restrict__ bc, const float* __restrict__ Wage,
    const float* __restrict__ bage, float* __restrict__ x)
{
    const int i = blockIdx.x;
    const int tid = threadIdx.x;
    __shared__ float cv[CSZ];
    if (tid < CSZ) cv[tid] = concepts[i * CSZ + tid];
    __syncthreads();
    const float agef = (float)i / 256.0f;
    for (int d = tid; d < D_DIM; d += 256) {
        const float4* wr = reinterpret_cast<const float4*>(Wc + (size_t)d * CSZ);
        const float4* c4 = reinterpret_cast<const float4*>(cv);
        float s = 0.f;
#pragma unroll
        for (int t = 0; t < CSZ / 4; t++) {
            const float4 w = wr[t], c = c4[t];
            s += w.x * c.x + w.y * c.y + w.z * c.z + w.w * c.w;
        }
        s += bc[d] + Wage[(size_t)d * AGE_V + i] + agef * Wage[(size_t)d * AGE_V + (AGE_V - 1)] + bage[d];
        x[(size_t)(i + 1) * D_DIM + d] = s;
    }
}

// ---------------- host launch ----------------------------------------------
extern "C" void kernel_launch(void* const* d_in, const int* in_sizes, int n_in,
                              void* d_out, int out_size)
{
    const float* observation = (const float*)d_in[0];
    const float* concepts    = (const float*)d_in[1];
    const float* W_core = (const float*)d_in[2];
    const float* b_core = (const float*)d_in[3];
    const float* W_cemb = (const float*)d_in[4];
    const float* b_cemb = (const float*)d_in[5];
    const float* W_age  = (const float*)d_in[6];
    const float* b_age  = (const float*)d_in[7];
    const float* Wq = (const float*)d_in[8];
    const float* bq = (const float*)d_in[9];
    const float* Wk = (const float*)d_in[10];
    const float* bk = (const float*)d_in[11];
    const float* Wv = (const float*)d_in[12];
    const float* bv = (const float*)d_in[13];
    const float* Wo = (const float*)d_in[14];
    const float* bo = (const float*)d_in[15];
    const float* ln1_g = (const float*)d_in[16];
    const float* ln1_b = (const float*)d_in[17];
    const float* W1 = (const float*)d_in[18];
    const float* b1 = (const float*)d_in[19];
    const float* W2 = (const float*)d_in[20];
    const float* b2 = (const float*)d_in[21];
    const float* ln2_g = (const float*)d_in[22];
    const float* ln2_b = (const float*)d_in[23];
    const float* W_concept = (const float*)d_in[24];
    const float* b_concept = (const float*)d_in[25];
    const float* W_out = (const float*)d_in[26];
    const float* b_out = (const float*)d_in[27];

    float *x, *q, *k, *v, *ao, *ffn, *part;
    cudaGetSymbolAddress((void**)&x, g_x);
    cudaGetSymbolAddress((void**)&q, g_q);
    cudaGetSymbolAddress((void**)&k, g_k);
    cudaGetSymbolAddress((void**)&v, g_v);
    cudaGetSymbolAddress((void**)&ao, g_ao);
    cudaGetSymbolAddress((void**)&ffn, g_ffn);
    cudaGetSymbolAddress((void**)&part, g_part);

    const int M = S_TOK;
    const dim3 blk(256);
    // y = 3: tiles 0,1 full 128-row (rows 0..255), tile 2 = slim (row 256)
    const dim3 grid_qkv(D_DIM / 64, 3, 3);        // 144
    const dim3 grid_o(D_DIM / 64, 3, 4);          // split-K=4, 192
    const dim3 grid_w1(HID / 64, 3, 1);           // 192
    const dim3 grid_w2(D_DIM / 64, 3, 4);         // split-K=4, 192
    const dim3 grid_attn(HEADS, (S_TOK + QT - 1) / QT);   // 16 x 17

    // --- embeddings ---
    matvec_kernel<<<D_DIM / 8, 256>>>(W_core, b_core, observation, x, D_DIM, OBS_N, 0);
    cemb_kernel<<<NC, 256>>>(concepts, W_cemb, b_cemb, W_age, b_age, x);

    // --- transformer layers ---
    for (int l = 0; l < NLAYER; l++) {
        const size_t od  = (size_t)l * D_DIM * D_DIM;
        const size_t ob  = (size_t)l * D_DIM;
        const size_t o1w = (size_t)l * HID * D_DIM;
        const size_t o1b = (size_t)l * HID;

        gemm_qkv_kernel<<<grid_qkv, blk>>>(x, Wq + od, Wk + od, Wv + od,
                                           bq + ob, bk + ob, bv + ob,
                                           q, k, v, M, D_DIM, D_DIM);

        attn3_kernel<<<grid_attn, 256>>>(q, k, v, ao);

        gemm_splitk_kernel<<<grid_o, blk>>>(ao, Wo + od, part, M, D_DIM, D_DIM, D_DIM / 4);
        combine_ln_kernel<<<M, 256>>>(part, 4, bo + ob, x, ln1_g + ob, ln1_b + ob, x, M);

        gemm_direct_kernel<<<grid_w1, blk>>>(x, W1 + o1w, b1 + o1b, ffn, M, HID, D_DIM, 1);
        gemm_splitk_kernel<<<grid_w2, blk>>>(ffn, W2 + o1w, part, M, D_DIM, HID, HID / 4);
        combine_ln_kernel<<<M, 256>>>(part, 4, b2 + ob, x, ln2_g + ob, ln2_b + ob, x, M);
    }

    // --- heads (node 0) -> d_out = [output(512) | new_concept(128)] ---
    float* out = (float*)d_out;
    heads_kernel<<<(OUT_N + CSZ) / 8, 256>>>(W_out, b_out, W_concept, b_concept, x, out);

    (void)in_sizes; (void)n_in; (void)out_size;
}

// round 12
// speedup vs baseline: 1.1013x; 1.1013x over previous
#include <cuda_runtime.h>
#include <math.h>
#include <stdint.h>

#define S_TOK 257
#define D_DIM 1024
#define HID 4096
#define NLAYER 12
#define NC 256
#define CSZ 128
#define AGE_V 258
#define OBS_N 2048
#define OUT_N 512
#define HEADS 16
#define DH 64

// ---------------- scratch (device globals; no allocation allowed) ----------
__device__ float g_x[S_TOK * D_DIM];
__device__ float g_q[S_TOK * D_DIM];
__device__ float g_k[S_TOK * D_DIM];
__device__ float g_v[S_TOK * D_DIM];
__device__ float g_ao[S_TOK * D_DIM];
__device__ float g_ffn[S_TOK * HID];
__device__ float g_part[4 * S_TOK * D_DIM];   // split-K partials (KS<=4)

// ---------------- helpers ---------------------------------------------------
__device__ __forceinline__ float warpMax(float v) {
#pragma unroll
    for (int o = 16; o; o >>= 1) v = fmaxf(v, __shfl_xor_sync(0xffffffffu, v, o));
    return v;
}
__device__ __forceinline__ float warpSum(float v) {
#pragma unroll
    for (int o = 16; o; o >>= 1) v += __shfl_xor_sync(0xffffffffu, v, o);
    return v;
}
__device__ __forceinline__ uint32_t pkh2(float a, float b) {   // lo=a, hi=b
    uint32_t r;
    asm("cvt.rn.f16x2.f32 %0, %1, %2;" : "=r"(r) : "f"(b), "f"(a));
    return r;
}
__device__ __forceinline__ uint32_t smem_u32p(const void* p) {
    uint32_t a;
    asm("{ .reg .u64 t; cvta.to.shared.u64 t, %1; cvt.u32.u64 %0, t; }" : "=r"(a) : "l"(p));
    return a;
}
__device__ __forceinline__ void mma16816(float (&d)[4], const uint32_t (&a)[4], const uint32_t (&b)[2]) {
    asm volatile(
        "mma.sync.aligned.m16n8k16.row.col.f32.f16.f16.f32 "
        "{%0,%1,%2,%3}, {%4,%5,%6,%7}, {%8,%9}, {%0,%1,%2,%3};\n"
        : "+f"(d[0]), "+f"(d[1]), "+f"(d[2]), "+f"(d[3])
        : "r"(a[0]), "r"(a[1]), "r"(a[2]), "r"(a[3]), "r"(b[0]), "r"(b[1]));
}
__device__ __forceinline__ void ldsm4(uint32_t& r0, uint32_t& r1, uint32_t& r2, uint32_t& r3,
                                      uint32_t addr) {
    asm volatile("ldmatrix.sync.aligned.m8n8.x4.shared.b16 {%0,%1,%2,%3}, [%4];"
                 : "=r"(r0), "=r"(r1), "=r"(r2), "=r"(r3) : "r"(addr));
}
__device__ __forceinline__ void ldsm2(uint32_t& r0, uint32_t& r1, uint32_t addr) {
    asm volatile("ldmatrix.sync.aligned.m8n8.x2.shared.b16 {%0,%1}, [%2];"
                 : "=r"(r0), "=r"(r1) : "r"(addr));
}
__device__ __forceinline__ void ldsm2t(uint32_t& r0, uint32_t& r1, uint32_t addr) {
    asm volatile("ldmatrix.sync.aligned.m8n8.x2.trans.shared.b16 {%0,%1}, [%2];"
                 : "=r"(r0), "=r"(r1) : "r"(addr));
}

// ============================================================================
// fp16 GEMM core, ldmatrix + double-buffered smem (one barrier per k-tile).
// Block 128x64, BK=32, 256 threads (8 warps 4x2, warp tile 32x32).
// ============================================================================
#define ROWW 20
#define A_U32 (128 * ROWW)
#define B_U32 (64 * ROWW)
#define A_BYTES (A_U32 * 4)
#define B_BYTES (B_U32 * 4)

__device__ __forceinline__ void f16_core128(
    const float* __restrict__ A, const float* __restrict__ B,
    int K, int bm, int bn, int kbeg, int ktiles,
    float (&acc)[2][4][4], uint32_t* __restrict__ As, uint32_t* __restrict__ Bs)
{
    const int tid = threadIdx.x;
    const int lane = tid & 31, wid = tid >> 5;
    const int wm = wid & 3, wn = wid >> 2;
    const int sub = lane >> 3, r8 = lane & 7;

    const uint32_t As_b = smem_u32p(As);
    const uint32_t Bs_b = smem_u32p(Bs);
    uint32_t a_addr[2];
#pragma unroll
    for (int mi = 0; mi < 2; mi++) {
        const int row = wm * 32 + mi * 16 + (sub & 1) * 8 + r8;
        a_addr[mi] = As_b + (row * ROWW + (sub >> 1) * 4) * 4;
    }
    uint32_t b_addr[2];
#pragma unroll
    for (int p = 0; p < 2; p++) {
        const int row = wn * 32 + p * 16 + (sub >> 1) * 8 + r8;
        b_addr[p] = Bs_b + (row * ROWW + (sub & 1) * 4) * 4;
    }

    int aoff[4];
    const float* aptr[4];
#pragma unroll
    for (int i = 0; i < 4; i++) {
        const int idx = tid + i * 256;
        const int row = idx >> 3, f = idx & 7;
        aoff[i] = row * ROWW + f * 2;
        aptr[i] = A + (size_t)(bm + row) * K + kbeg + f * 4;
    }
    int boff[2];
    const float* bptr[2];
#pragma unroll
    for (int i = 0; i < 2; i++) {
        const int idx = tid + i * 256;
        const int row = idx >> 3, f = idx & 7;
        boff[i] = row * ROWW + f * 2;
        bptr[i] = B + (size_t)(bn + row) * K + kbeg + f * 4;
    }

    float4 pa[4], pb[2];
#pragma unroll
    for (int i = 0; i < 4; i++) pa[i] = *(const float4*)(aptr[i]);
#pragma unroll
    for (int i = 0; i < 2; i++) pb[i] = *(const float4*)(bptr[i]);
#pragma unroll
    for (int i = 0; i < 4; i++)
        *(uint2*)&As[aoff[i]] = make_uint2(pkh2(pa[i].x, pa[i].y), pkh2(pa[i].z, pa[i].w));
#pragma unroll
    for (int i = 0; i < 2; i++)
        *(uint2*)&Bs[boff[i]] = make_uint2(pkh2(pb[i].x, pb[i].y), pkh2(pb[i].z, pb[i].w));
    __syncthreads();

    int buf = 0;
    for (int kt = 0; kt < ktiles; kt++) {
        const bool has_next = (kt + 1 < ktiles);
        if (has_next) {
            const int off = (kt + 1) * 32;
#pragma unroll
            for (int i = 0; i < 4; i++) pa[i] = *(const float4*)(aptr[i] + off);
#pragma unroll
            for (int i = 0; i < 2; i++) pb[i] = *(const float4*)(bptr[i] + off);
        }
        const uint32_t a_bo = buf ? A_BYTES : 0;
        const uint32_t b_bo = buf ? B_BYTES : 0;
#pragma unroll
        for (int ks = 0; ks < 2; ks++) {
            const uint32_t koff = ks * 8 * 4;
            uint32_t af[2][4], bq[2][4];
#pragma unroll
            for (int mi = 0; mi < 2; mi++)
                ldsm4(af[mi][0], af[mi][1], af[mi][2], af[mi][3], a_addr[mi] + a_bo + koff);
#pragma unroll
            for (int p = 0; p < 2; p++)
                ldsm4(bq[p][0], bq[p][1], bq[p][2], bq[p][3], b_addr[p] + b_bo + koff);
#pragma unroll
            for (int mi = 0; mi < 2; mi++) {
#pragma unroll
                for (int p = 0; p < 2; p++) {
                    const uint32_t b0[2] = {bq[p][0], bq[p][1]};
                    const uint32_t b1[2] = {bq[p][2], bq[p][3]};
                    mma16816(acc[mi][p * 2 + 0], af[mi], b0);
                    mma16816(acc[mi][p * 2 + 1], af[mi], b1);
                }
            }
        }
        if (has_next) {
            const int nb = buf ^ 1;
            uint32_t* An = As + (nb ? A_U32 : 0);
            uint32_t* Bn = Bs + (nb ? B_U32 : 0);
#pragma unroll
            for (int i = 0; i < 4; i++)
                *(uint2*)&An[aoff[i]] = make_uint2(pkh2(pa[i].x, pa[i].y), pkh2(pa[i].z, pa[i].w));
#pragma unroll
            for (int i = 0; i < 2; i++)
                *(uint2*)&Bn[boff[i]] = make_uint2(pkh2(pb[i].x, pb[i].y), pkh2(pb[i].z, pb[i].w));
            __syncthreads();
            buf = nb;
        }
    }
}

#define EPI128_VARS \
    const int lane = threadIdx.x & 31, wid = threadIdx.x >> 5; \
    const int wm = wid & 3, wn = wid >> 2; \
    const int fr = lane >> 2, fc = lane & 3;

// ---- slim path: compute single row (row 256) as fp32 matvec -----------------
__device__ __forceinline__ void slim_row(
    const float* __restrict__ Arow, const float* __restrict__ B,
    int K, int bn, int kbeg, int klen,
    float* xs, float* outvals, int* outcols)
{
    const int tid = threadIdx.x;
    const int wid = tid >> 5, lane = tid & 31;
    const int k4 = klen >> 2;
    for (int i = tid; i < k4; i += 256)
        ((float4*)xs)[i] = ((const float4*)Arow)[i];
    __syncthreads();
#pragma unroll
    for (int cc = 0; cc < 8; cc++) {
        const int col = bn + wid * 8 + cc;
        const float4* wr = (const float4*)(B + (size_t)col * K + kbeg);
        float s = 0.f;
        for (int kb = lane; kb < k4; kb += 32) {
            const float4 w = wr[kb], xv = ((const float4*)xs)[kb];
            s += w.x * xv.x + w.y * xv.y + w.z * xv.z + w.w * xv.w;
        }
        s = warpSum(s);
        outvals[cc] = s;
        outcols[cc] = col;
    }
}

// ---- fused QKV ---------------------------------------------------------------
__global__ __launch_bounds__(256) void gemm_qkv_kernel(
    const float* __restrict__ A,
    const float* __restrict__ Wq_, const float* __restrict__ Wk_, const float* __restrict__ Wv_,
    const float* __restrict__ bq_, const float* __restrict__ bk_, const float* __restrict__ bv_,
    float* __restrict__ Q, float* __restrict__ Ko, float* __restrict__ V,
    int M, int N, int K)
{
    __shared__ uint32_t As[2 * A_U32];
    __shared__ uint32_t Bs[2 * B_U32];
    const int z = blockIdx.z;
    const float* B    = (z == 0) ? Wq_ : (z == 1) ? Wk_ : Wv_;
    const float* bias = (z == 0) ? bq_ : (z == 1) ? bk_ : bv_;
    float* C          = (z == 0) ? Q   : (z == 1) ? Ko  : V;
    const int bn = blockIdx.x * 64;

    if (blockIdx.y == 2) {
        float vals[8]; int cols[8];
        slim_row(A + (size_t)256 * K, B, K, bn, 0, K, (float*)As, vals, cols);
        if ((threadIdx.x & 31) == 0) {
#pragma unroll
            for (int cc = 0; cc < 8; cc++)
                C[(size_t)256 * N + cols[cc]] = vals[cc] + bias[cols[cc]];
        }
        return;
    }

    const int bm = blockIdx.y * 128;
    float acc[2][4][4] = {};
    f16_core128(A, B, K, bm, bn, 0, K / 32, acc, As, Bs);

    EPI128_VARS
#pragma unroll
    for (int mi = 0; mi < 2; mi++)
#pragma unroll
        for (int ni = 0; ni < 4; ni++) {
            const int r = bm + wm * 32 + mi * 16 + fr;
            const int c = bn + wn * 32 + ni * 8 + fc * 2;
            const float bx = bias[c], by = bias[c + 1];
            float2 o0 = {acc[mi][ni][0] + bx, acc[mi][ni][1] + by};
            float2 o1 = {acc[mi][ni][2] + bx, acc[mi][ni][3] + by};
            *(float2*)(C + (size_t)r * N + c) = o0;
            *(float2*)(C + (size_t)(r + 8) * N + c) = o1;
        }
}

// ---- direct GEMM with bias (+relu) -------------------------------------------
__global__ __launch_bounds__(256) void gemm_direct_kernel(
    const float* __restrict__ A, const float* __restrict__ B,
    const float* __restrict__ bias, float* __restrict__ C,
    int M, int N, int K, int relu_flag)
{
    __shared__ uint32_t As[2 * A_U32];
    __shared__ uint32_t Bs[2 * B_U32];
    const int bn = blockIdx.x * 64;

    if (blockIdx.y == 2) {
        float vals[8]; int cols[8];
        slim_row(A + (size_t)256 * K, B, K, bn, 0, K, (float*)As, vals, cols);
        if ((threadIdx.x & 31) == 0) {
#pragma unroll
            for (int cc = 0; cc < 8; cc++) {
                float s = vals[cc] + bias[cols[cc]];
                if (relu_flag) s = fmaxf(s, 0.f);
                C[(size_t)256 * N + cols[cc]] = s;
            }
        }
        return;
    }

    const int bm = blockIdx.y * 128;
    float acc[2][4][4] = {};
    f16_core128(A, B, K, bm, bn, 0, K / 32, acc, As, Bs);

    EPI128_VARS
#pragma unroll
    for (int mi = 0; mi < 2; mi++)
#pragma unroll
        for (int ni = 0; ni < 4; ni++) {
            const int r = bm + wm * 32 + mi * 16 + fr;
            const int c = bn + wn * 32 + ni * 8 + fc * 2;
            const float bx = bias[c], by = bias[c + 1];
            float2 o0 = {acc[mi][ni][0] + bx, acc[mi][ni][1] + by};
            float2 o1 = {acc[mi][ni][2] + bx, acc[mi][ni][3] + by};
            if (relu_flag) {
                o0.x = fmaxf(o0.x, 0.f); o0.y = fmaxf(o0.y, 0.f);
                o1.x = fmaxf(o1.x, 0.f); o1.y = fmaxf(o1.y, 0.f);
            }
            *(float2*)(C + (size_t)r * N + c) = o0;
            *(float2*)(C + (size_t)(r + 8) * N + c) = o1;
        }
}

// ---- split-K GEMM (raw partials) ---------------------------------------------
__global__ __launch_bounds__(256) void gemm_splitk_kernel(
    const float* __restrict__ A, const float* __restrict__ B,
    float* __restrict__ part, int M, int N, int K, int klen)
{
    __shared__ uint32_t As[2 * A_U32];
    __shared__ uint32_t Bs[2 * B_U32];
    const int bn = blockIdx.x * 64;
    const int z = blockIdx.z;
    float* C = part + (size_t)z * M * N;

    if (blockIdx.y == 2) {
        float vals[8]; int cols[8];
        slim_row(A + (size_t)256 * K + z * klen, B, K, bn, z * klen, klen, (float*)As, vals, cols);
        if ((threadIdx.x & 31) == 0) {
#pragma unroll
            for (int cc = 0; cc < 8; cc++)
                C[(size_t)256 * N + cols[cc]] = vals[cc];
        }
        return;
    }

    const int bm = blockIdx.y * 128;
    float acc[2][4][4] = {};
    f16_core128(A, B, K, bm, bn, z * klen, klen / 32, acc, As, Bs);

    EPI128_VARS
#pragma unroll
    for (int mi = 0; mi < 2; mi++)
#pragma unroll
        for (int ni = 0; ni < 4; ni++) {
            const int r = bm + wm * 32 + mi * 16 + fr;
            const int c = bn + wn * 32 + ni * 8 + fc * 2;
            float2 o0 = {acc[mi][ni][0], acc[mi][ni][1]};
            float2 o1 = {acc[mi][ni][2], acc[mi][ni][3]};
            *(float2*)(C + (size_t)r * N + c) = o0;
            *(float2*)(C + (size_t)(r + 8) * N + c) = o1;
        }
}

// ---- fused combine(split-K) + bias + residual + LayerNorm --------------------
__global__ __launch_bounds__(256) void combine_ln_kernel(
    const float* __restrict__ part, int KS,
    const float* __restrict__ bias, const float* __restrict__ res,
    const float* __restrict__ g, const float* __restrict__ b,
    float* __restrict__ out, int M)
{
    const int row = blockIdx.x;
    const int tid = threadIdx.x;
    const int lane = tid & 31, warp = tid >> 5;
    __shared__ float rs[8], rs2[8];
    __shared__ float smv[2];

    float4 s = ((const float4*)(part + (size_t)row * D_DIM))[tid];
    for (int z = 1; z < KS; z++) {
        const float4 t = ((const float4*)(part + ((size_t)z * M + row) * D_DIM))[tid];
        s.x += t.x; s.y += t.y; s.z += t.z; s.w += t.w;
    }
    const float4 b4 = ((const float4*)bias)[tid];
    s.x += b4.x; s.y += b4.y; s.z += b4.z; s.w += b4.w;
    const float4 r4 = ((const float4*)(res + (size_t)row * D_DIM))[tid];
    s.x += r4.x; s.y += r4.y; s.z += r4.z; s.w += r4.w;

    float sum = s.x + s.y + s.z + s.w;
    float sq = s.x * s.x + s.y * s.y + s.z * s.z + s.w * s.w;
    sum = warpSum(sum); sq = warpSum(sq);
    if (lane == 0) { rs[warp] = sum; rs2[warp] = sq; }
    __syncthreads();
    if (warp == 0) {
        float t = (lane < 8) ? rs[lane] : 0.f;
        float t2 = (lane < 8) ? rs2[lane] : 0.f;
        t = warpSum(t); t2 = warpSum(t2);
        if (lane == 0) {
            const float mean = t * (1.0f / D_DIM);
            const float var = t2 * (1.0f / D_DIM) - mean * mean;
            smv[0] = mean;
            smv[1] = rsqrtf(var + 1e-5f);
        }
    }
    __syncthreads();
    const float mean = smv[0], inv = smv[1];
    const float4 g4 = ((const float4*)g)[tid];
    const float4 be4 = ((const float4*)b)[tid];
    float4 o;
    o.x = (s.x - mean) * inv * g4.x + be4.x;
    o.y = (s.y - mean) * inv * g4.y + be4.y;
    o.z = (s.z - mean) * inv * g4.z + be4.z;
    o.w = (s.w - mean) * inv * g4.w + be4.w;
    ((float4*)(out + (size_t)row * D_DIM))[tid] = o;
}

// ============================================================================
// Tensor-core attention: block per (head, 16-query tile), 256 threads.
// Phase1 QK^T and Phase3 P@V via m16n8k16; softmax fp32.
// ============================================================================
#define QT 16
#define TROWW 36            // u32 stride for half tiles (32 data + 4 pad)
#define SCW 324

__global__ __launch_bounds__(256) void attn_mma_kernel(
    const float* __restrict__ q, const float* __restrict__ k,
    const float* __restrict__ v, float* __restrict__ o)
{
    const int h = blockIdx.x;
    const int qt = blockIdx.y * QT;
    const int tid = threadIdx.x, lane = tid & 31, warp = tid >> 5;
    const int sub = lane >> 3, r8 = lane & 7;

    __shared__ uint32_t Qh[QT][TROWW];
    __shared__ uint32_t Th[64][TROWW];
    __shared__ uint32_t Ph[QT][TROWW];
    __shared__ float sc[QT][SCW];
    __shared__ float inv_s[QT];

    const int nq = min(QT, S_TOK - qt);
    const uint32_t Qh_b = smem_u32p(&Qh[0][0]);
    const uint32_t Th_b = smem_u32p(&Th[0][0]);
    const uint32_t Ph_b = smem_u32p(&Ph[0][0]);

    // load Q tile -> half (16 rows x 16 float4 groups = 256 threads)
    {
        const int r = tid >> 4, f = tid & 15;
        float4 val = (r < nq) ? *(const float4*)(q + (size_t)(qt + r) * D_DIM + h * DH + f * 4)
                              : make_float4(0.f, 0.f, 0.f, 0.f);
        Qh[r][f * 2]     = pkh2(val.x, val.y);
        Qh[r][f * 2 + 1] = pkh2(val.z, val.w);
    }
    __syncthreads();

    // persistent A fragments from Q (4 k-steps over DH=64)
    uint32_t qaf[4][4];
    {
        const uint32_t a_base = Qh_b + (((sub & 1) * 8 + r8) * TROWW + (sub >> 1) * 4) * 4;
#pragma unroll
        for (int kc = 0; kc < 4; kc++)
            ldsm4(qaf[kc][0], qaf[kc][1], qaf[kc][2], qaf[kc][3], a_base + kc * 32);
    }

    const int fr = lane >> 2, fc = lane & 3;

    // ---------------- phase 1: scores ----------------
    for (int j0 = 0; j0 < S_TOK; j0 += 64) {
        const int jn = min(64, S_TOK - j0);
        __syncthreads();
#pragma unroll
        for (int i = 0; i < 4; i++) {
            const int idx = tid + i * 256;
            const int r = idx >> 4, f = idx & 15;
            float4 val = (r < jn) ? *(const float4*)(k + (size_t)(j0 + r) * D_DIM + h * DH + f * 4)
                                  : make_float4(0.f, 0.f, 0.f, 0.f);
            Th[r][f * 2]     = pkh2(val.x, val.y);
            Th[r][f * 2 + 1] = pkh2(val.z, val.w);
        }
        __syncthreads();
        float dacc[4] = {0.f, 0.f, 0.f, 0.f};
        // B addresses (x2): lanes 0-7 rows jb+r8 @+0B, lanes 8-15 rows jb+r8 @+16B
        const uint32_t b_base = Th_b + ((warp * 8 + r8) * TROWW + (sub & 1) * 4) * 4;
#pragma unroll
        for (int kc = 0; kc < 4; kc++) {
            uint32_t bf0, bf1;
            ldsm2(bf0, bf1, b_base + kc * 32);
            const uint32_t bf[2] = {bf0, bf1};
            mma16816(dacc, qaf[kc], bf);
        }
        const int cb = j0 + warp * 8 + fc * 2;
        sc[fr][cb]         = dacc[0] * 0.125f;
        sc[fr][cb + 1]     = dacc[1] * 0.125f;
        sc[fr + 8][cb]     = dacc[2] * 0.125f;
        sc[fr + 8][cb + 1] = dacc[3] * 0.125f;
    }
    __syncthreads();

    // ---------------- phase 2: softmax ----------------
#pragma unroll
    for (int ri = 0; ri < 2; ri++) {
        const int r = warp * 2 + ri;
        if (r < nq) {
            float m = -1e30f;
            for (int j = lane; j < S_TOK; j += 32) m = fmaxf(m, sc[r][j]);
            m = warpMax(m);
            float ssum = 0.f;
            for (int j = lane; j < S_TOK; j += 32) {
                const float e = __expf(sc[r][j] - m);
                sc[r][j] = e;
                ssum += e;
            }
            ssum = warpSum(ssum);
            if (lane == 0) inv_s[r] = 1.0f / ssum;
        }
    }

    // ---------------- phase 3: P @ V ----------------
    float oacc[4] = {0.f, 0.f, 0.f, 0.f};
    for (int j0 = 0; j0 < S_TOK; j0 += 64) {
        const int jn = min(64, S_TOK - j0);
        __syncthreads();
        // load V tile
#pragma unroll
        for (int i = 0; i < 4; i++) {
            const int idx = tid + i * 256;
            const int r = idx >> 4, f = idx & 15;
            float4 val = (r < jn) ? *(const float4*)(v + (size_t)(j0 + r) * D_DIM + h * DH + f * 4)
                                  : make_float4(0.f, 0.f, 0.f, 0.f);
            Th[r][f * 2]     = pkh2(val.x, val.y);
            Th[r][f * 2 + 1] = pkh2(val.z, val.w);
        }
        // convert P chunk to half (predicated on j < S_TOK)
        {
            const int r = tid >> 4, gp = tid & 15;
            const int jb = j0 + gp * 4;
            const float p0 = (jb + 0 < S_TOK) ? sc[r][jb + 0] : 0.f;
            const float p1 = (jb + 1 < S_TOK) ? sc[r][jb + 1] : 0.f;
            const float p2 = (jb + 2 < S_TOK) ? sc[r][jb + 2] : 0.f;
            const float p3 = (jb + 3 < S_TOK) ? sc[r][jb + 3] : 0.f;
            Ph[r][gp * 2]     = pkh2(p0, p1);
            Ph[r][gp * 2 + 1] = pkh2(p2, p3);
        }
        __syncthreads();
        // A frags from Ph, B frags from Th via trans ldmatrix
        const uint32_t pa_base = Ph_b + (((sub & 1) * 8 + r8) * TROWW + (sub >> 1) * 4) * 4;
        // trans addresses: lanes 0-7 rows kc*16+r8, lanes 8-15 rows kc*16+8+r8, col halves warp*8
        const uint32_t bt_base = Th_b + (((sub & 1) * 8 + r8) * TROWW) * 4 + warp * 16;
#pragma unroll
        for (int kc = 0; kc < 4; kc++) {
            uint32_t paf[4];
            ldsm4(paf[0], paf[1], paf[2], paf[3], pa_base + kc * 32);
            uint32_t bf0, bf1;
            ldsm2t(bf0, bf1, bt_base + kc * 16 * TROWW * 4);
            const uint32_t bf[2] = {bf0, bf1};
            mma16816(oacc, paf, bf);
        }
    }

    // output: rows fr, fr+8; cols d = warp*8 + fc*2
    const int d = warp * 8 + fc * 2;
    if (fr < nq) {
        const float iv = inv_s[fr];
        float2 o0 = {oacc[0] * iv, oacc[1] * iv};
        *(float2*)(o + (size_t)(qt + fr) * D_DIM + h * DH + d) = o0;
    }
    if (fr + 8 < nq) {
        const float iv = inv_s[fr + 8];
        float2 o1 = {oacc[2] * iv, oacc[3] * iv};
        *(float2*)(o + (size_t)(qt + fr + 8) * D_DIM + h * DH + d) = o1;
    }
}

// ---------------- matvec (embeddings) ---------------------------------------
__global__ __launch_bounds__(256) void matvec_kernel(
    const float* __restrict__ W, const float* __restrict__ bias,
    const float* __restrict__ x, float* __restrict__ out,
    int N, int K, int act)
{
    __shared__ float xs[OBS_N];
    const int tid = threadIdx.x;
    for (int i = tid; i < K; i += 256) xs[i] = x[i];
    __syncthreads();
    const int warp = tid >> 5, lane = tid & 31;
    const int n = blockIdx.x * 8 + warp;
    if (n >= N) return;
    const float4* wr = reinterpret_cast<const float4*>(W + (size_t)n * K);
    const float4* x4 = reinterpret_cast<const float4*>(xs);
    float s = 0.f;
    const int K4 = K >> 2;
    for (int kb = lane; kb < K4; kb += 32) {
        const float4 w = wr[kb], xv = x4[kb];
        s += w.x * xv.x + w.y * xv.y + w.z * xv.z + w.w * xv.w;
    }
    s = warpSum(s);
    if (lane == 0) {
        s += bias[n];
        if (act == 1) s = fmaxf(s, 0.f);
        else if (act == 2) s = tanhf(s);
        out[n] = s;
    }
}

// ---------------- fused output heads (W_out relu | W_concept tanh) ----------
__global__ __launch_bounds__(256) void heads_kernel(
    const float* __restrict__ W_out, const float* __restrict__ b_out,
    const float* __restrict__ W_con, const float* __restrict__ b_con,
    const float* __restrict__ x, float* __restrict__ out)
{
    __shared__ float xs[D_DIM];
    const int tid = threadIdx.x;
    for (int i = tid; i < D_DIM; i += 256) xs[i] = x[i];
    __syncthreads();
    const int warp = tid >> 5, lane = tid & 31;
    const int n = blockIdx.x * 8 + warp;
    const bool is_out = (n < OUT_N);
    const int nn = is_out ? n : n - OUT_N;
    const float* W = is_out ? W_out : W_con;
    const float4* wr = reinterpret_cast<const float4*>(W + (size_t)nn * D_DIM);
    const float4* x4 = reinterpret_cast<const float4*>(xs);
    float s = 0.f;
#pragma unroll 4
    for (int kb = lane; kb < D_DIM / 4; kb += 32) {
        const float4 w = wr[kb], xv = x4[kb];
        s += w.x * xv.x + w.y * xv.y + w.z * xv.z + w.w * xv.w;
    }
    s = warpSum(s);
    if (lane == 0) {
        if (is_out) out[n] = fmaxf(s + b_out[nn], 0.f);
        else        out[n] = tanhf(s + b_con[nn]);
    }
}

// ---------------- concept embedding (rows 1..256 of x) ---------------------
__global__ __launch_bounds__(256) void cemb_kernel(
    const float* __restrict__ concepts, const float* __restrict__ Wc,
    const float* __restrict__ bc, const float* __restrict__ Wage,
    const float* __restrict__ bage, float* __restrict__ x)
{
    const int i = blockIdx.x;
    const int tid = threadIdx.x;
    __shared__ float cv[CSZ];
    if (tid < CSZ) cv[tid] = concepts[i * CSZ + tid];
    __syncthreads();
    const float agef = (float)i / 256.0f;
    for (int d = tid; d < D_DIM; d += 256) {
        const float4* wr = reinterpret_cast<const float4*>(Wc + (size_t)d * CSZ);
        const float4* c4 = reinterpret_cast<const float4*>(cv);
        float s = 0.f;
#pragma unroll
        for (int t = 0; t < CSZ / 4; t++) {
            const float4 w = wr[t], c = c4[t];
            s += w.x * c.x + w.y * c.y + w.z * c.z + w.w * c.w;
        }
        s += bc[d] + Wage[(size_t)d * AGE_V + i] + agef * Wage[(size_t)d * AGE_V + (AGE_V - 1)] + bage[d];
        x[(size_t)(i + 1) * D_DIM + d] = s;
    }
}

// ---------------- host launch ----------------------------------------------
extern "C" void kernel_launch(void* const* d_in, const int* in_sizes, int n_in,
                              void* d_out, int out_size)
{
    const float* observation = (const float*)d_in[0];
    const float* concepts    = (const float*)d_in[1];
    const float* W_core = (const float*)d_in[2];
    const float* b_core = (const float*)d_in[3];
    const float* W_cemb = (const float*)d_in[4];
    const float* b_cemb = (const float*)d_in[5];
    const float* W_age  = (const float*)d_in[6];
    const float* b_age  = (const float*)d_in[7];
    const float* Wq = (const float*)d_in[8];
    const float* bq = (const float*)d_in[9];
    const float* Wk = (const float*)d_in[10];
    const float* bk = (const float*)d_in[11];
    const float* Wv = (const float*)d_in[12];
    const float* bv = (const float*)d_in[13];
    const float* Wo = (const float*)d_in[14];
    const float* bo = (const float*)d_in[15];
    const float* ln1_g = (const float*)d_in[16];
    const float* ln1_b = (const float*)d_in[17];
    const float* W1 = (const float*)d_in[18];
    const float* b1 = (const float*)d_in[19];
    const float* W2 = (const float*)d_in[20];
    const float* b2 = (const float*)d_in[21];
    const float* ln2_g = (const float*)d_in[22];
    const float* ln2_b = (const float*)d_in[23];
    const float* W_concept = (const float*)d_in[24];
    const float* b_concept = (const float*)d_in[25];
    const float* W_out = (const float*)d_in[26];
    const float* b_out = (const float*)d_in[27];

    float *x, *q, *k, *v, *ao, *ffn, *part;
    cudaGetSymbolAddress((void**)&x, g_x);
    cudaGetSymbolAddress((void**)&q, g_q);
    cudaGetSymbolAddress((void**)&k, g_k);
    cudaGetSymbolAddress((void**)&v, g_v);
    cudaGetSymbolAddress((void**)&ao, g_ao);
    cudaGetSymbolAddress((void**)&ffn, g_ffn);
    cudaGetSymbolAddress((void**)&part, g_part);

    const int M = S_TOK;
    const dim3 blk(256);
    const dim3 grid_qkv(D_DIM / 64, 3, 3);
    const dim3 grid_o(D_DIM / 64, 3, 4);
    const dim3 grid_w1(HID / 64, 3, 1);
    const dim3 grid_w2(D_DIM / 64, 3, 4);
    const dim3 grid_attn(HEADS, (S_TOK + QT - 1) / QT);

    // --- embeddings ---
    matvec_kernel<<<D_DIM / 8, 256>>>(W_core, b_core, observation, x, D_DIM, OBS_N, 0);
    cemb_kernel<<<NC, 256>>>(concepts, W_cemb, b_cemb, W_age, b_age, x);

    // --- transformer layers ---
    for (int l = 0; l < NLAYER; l++) {
        const size_t od  = (size_t)l * D_DIM * D_DIM;
        const size_t ob  = (size_t)l * D_DIM;
        const size_t o1w = (size_t)l * HID * D_DIM;
        const size_t o1b = (size_t)l * HID;

        gemm_qkv_kernel<<<grid_qkv, blk>>>(x, Wq + od, Wk + od, Wv + od,
                                           bq + ob, bk + ob, bv + ob,
                                           q, k, v, M, D_DIM, D_DIM);

        attn_mma_kernel<<<grid_attn, 256>>>(q, k, v, ao);

        gemm_splitk_kernel<<<grid_o, blk>>>(ao, Wo + od, part, M, D_DIM, D_DIM, D_DIM / 4);
        combine_ln_kernel<<<M, 256>>>(part, 4, bo + ob, x, ln1_g + ob, ln1_b + ob, x, M);

        gemm_direct_kernel<<<grid_w1, blk>>>(x, W1 + o1w, b1 + o1b, ffn, M, HID, D_DIM, 1);
        gemm_splitk_kernel<<<grid_w2, blk>>>(ffn, W2 + o1w, part, M, D_DIM, HID, HID / 4);
        combine_ln_kernel<<<M, 256>>>(part, 4, b2 + ob, x, ln2_g + ob, ln2_b + ob, x, M);
    }

    // --- heads (node 0) -> d_out = [output(512) | new_concept(128)] ---
    float* out = (float*)d_out;
    heads_kernel<<<(OUT_N + CSZ) / 8, 256>>>(W_out, b_out, W_concept, b_concept, x, out);

    (void)in_sizes; (void)n_in; (void)out_size;
}

// round 13
// speedup vs baseline: 1.3352x; 1.2124x over previous
#include <cuda_runtime.h>
#include <math.h>
#include <stdint.h>

#define S_TOK 257
#define D_DIM 1024
#define HID 4096
#define NLAYER 12
#define NC 256
#define CSZ 128
#define AGE_V 258
#define OBS_N 2048
#define OUT_N 512
#define HEADS 16
#define DH 64

// ---------------- scratch (device globals; no allocation allowed) ----------
__device__ float g_x[S_TOK * D_DIM];
__device__ float g_q[S_TOK * D_DIM];
__device__ float g_k[S_TOK * D_DIM];
__device__ float g_v[S_TOK * D_DIM];
__device__ float g_ao[S_TOK * D_DIM];
__device__ float g_ffn[S_TOK * HID];
__device__ float g_part[4 * S_TOK * D_DIM];   // split-K partials (KS<=4)

// ---------------- helpers ---------------------------------------------------
__device__ __forceinline__ float warpMax(float v) {
#pragma unroll
    for (int o = 16; o; o >>= 1) v = fmaxf(v, __shfl_xor_sync(0xffffffffu, v, o));
    return v;
}
__device__ __forceinline__ float warpSum(float v) {
#pragma unroll
    for (int o = 16; o; o >>= 1) v += __shfl_xor_sync(0xffffffffu, v, o);
    return v;
}
__device__ __forceinline__ uint32_t pkh2(float a, float b) {   // lo=a, hi=b
    uint32_t r;
    asm("cvt.rn.f16x2.f32 %0, %1, %2;" : "=r"(r) : "f"(b), "f"(a));
    return r;
}
__device__ __forceinline__ uint32_t smem_u32p(const void* p) {
    uint32_t a;
    asm("{ .reg .u64 t; cvta.to.shared.u64 t, %1; cvt.u32.u64 %0, t; }" : "=r"(a) : "l"(p));
    return a;
}
__device__ __forceinline__ void mma16816(float (&d)[4], const uint32_t (&a)[4], const uint32_t (&b)[2]) {
    asm volatile(
        "mma.sync.aligned.m16n8k16.row.col.f32.f16.f16.f32 "
        "{%0,%1,%2,%3}, {%4,%5,%6,%7}, {%8,%9}, {%0,%1,%2,%3};\n"
        : "+f"(d[0]), "+f"(d[1]), "+f"(d[2]), "+f"(d[3])
        : "r"(a[0]), "r"(a[1]), "r"(a[2]), "r"(a[3]), "r"(b[0]), "r"(b[1]));
}
__device__ __forceinline__ void ldsm4(uint32_t& r0, uint32_t& r1, uint32_t& r2, uint32_t& r3,
                                      uint32_t addr) {
    asm volatile("ldmatrix.sync.aligned.m8n8.x4.shared.b16 {%0,%1,%2,%3}, [%4];"
                 : "=r"(r0), "=r"(r1), "=r"(r2), "=r"(r3) : "r"(addr));
}
__device__ __forceinline__ void ldsm2(uint32_t& r0, uint32_t& r1, uint32_t addr) {
    asm volatile("ldmatrix.sync.aligned.m8n8.x2.shared.b16 {%0,%1}, [%2];"
                 : "=r"(r0), "=r"(r1) : "r"(addr));
}
__device__ __forceinline__ void ldsm2t(uint32_t& r0, uint32_t& r1, uint32_t addr) {
    asm volatile("ldmatrix.sync.aligned.m8n8.x2.trans.shared.b16 {%0,%1}, [%2];"
                 : "=r"(r0), "=r"(r1) : "r"(addr));
}

// ============================================================================
// fp16 GEMM core, ldmatrix + double-buffered smem + DEPTH-2 register prefetch
// (loads for tile kt+2 issued at tile kt -> DRAM latency covered ~2 tiles).
// Block 128x64, BK=32, 256 threads (8 warps 4x2, warp tile 32x32).
// ============================================================================
#define ROWW 20
#define A_U32 (128 * ROWW)
#define B_U32 (64 * ROWW)
#define A_BYTES (A_U32 * 4)
#define B_BYTES (B_U32 * 4)

__device__ __forceinline__ void f16_core128(
    const float* __restrict__ A, const float* __restrict__ B,
    int K, int bm, int bn, int kbeg, int ktiles,
    float (&acc)[2][4][4], uint32_t* __restrict__ As, uint32_t* __restrict__ Bs)
{
    const int tid = threadIdx.x;
    const int lane = tid & 31, wid = tid >> 5;
    const int wm = wid & 3, wn = wid >> 2;
    const int sub = lane >> 3, r8 = lane & 7;

    const uint32_t As_b = smem_u32p(As);
    const uint32_t Bs_b = smem_u32p(Bs);
    uint32_t a_addr[2];
#pragma unroll
    for (int mi = 0; mi < 2; mi++) {
        const int row = wm * 32 + mi * 16 + (sub & 1) * 8 + r8;
        a_addr[mi] = As_b + (row * ROWW + (sub >> 1) * 4) * 4;
    }
    uint32_t b_addr[2];
#pragma unroll
    for (int p = 0; p < 2; p++) {
        const int row = wn * 32 + p * 16 + (sub >> 1) * 8 + r8;
        b_addr[p] = Bs_b + (row * ROWW + (sub & 1) * 4) * 4;
    }

    int aoff[4];
    const float* aptr[4];
#pragma unroll
    for (int i = 0; i < 4; i++) {
        const int idx = tid + i * 256;
        const int row = idx >> 3, f = idx & 7;
        aoff[i] = row * ROWW + f * 2;
        aptr[i] = A + (size_t)(bm + row) * K + kbeg + f * 4;
    }
    int boff[2];
    const float* bptr[2];
#pragma unroll
    for (int i = 0; i < 2; i++) {
        const int idx = tid + i * 256;
        const int row = idx >> 3, f = idx & 7;
        boff[i] = row * ROWW + f * 2;
        bptr[i] = B + (size_t)(bn + row) * K + kbeg + f * 4;
    }

    float4 RaA[4], RaB[2], RbA[4], RbB[2];

#define DO_LDG(T, RA, RB) do { \
    const int _off = (T) * 32; \
    _Pragma("unroll") for (int i = 0; i < 4; i++) RA[i] = *(const float4*)(aptr[i] + _off); \
    _Pragma("unroll") for (int i = 0; i < 2; i++) RB[i] = *(const float4*)(bptr[i] + _off); \
} while (0)

#define DO_STS(BSEL, RA, RB) do { \
    uint32_t* _An = As + ((BSEL) ? A_U32 : 0); \
    uint32_t* _Bn = Bs + ((BSEL) ? B_U32 : 0); \
    _Pragma("unroll") for (int i = 0; i < 4; i++) \
        *(uint2*)&_An[aoff[i]] = make_uint2(pkh2(RA[i].x, RA[i].y), pkh2(RA[i].z, RA[i].w)); \
    _Pragma("unroll") for (int i = 0; i < 2; i++) \
        *(uint2*)&_Bn[boff[i]] = make_uint2(pkh2(RB[i].x, RB[i].y), pkh2(RB[i].z, RB[i].w)); \
} while (0)

#define DO_MMA(BSEL) do { \
    const uint32_t _abo = (BSEL) ? (uint32_t)A_BYTES : 0u; \
    const uint32_t _bbo = (BSEL) ? (uint32_t)B_BYTES : 0u; \
    _Pragma("unroll") for (int ks = 0; ks < 2; ks++) { \
        const uint32_t _ko = ks * 8 * 4; \
        uint32_t _af[2][4], _bq[2][4]; \
        _Pragma("unroll") for (int mi = 0; mi < 2; mi++) \
            ldsm4(_af[mi][0], _af[mi][1], _af[mi][2], _af[mi][3], a_addr[mi] + _abo + _ko); \
        _Pragma("unroll") for (int p = 0; p < 2; p++) \
            ldsm4(_bq[p][0], _bq[p][1], _bq[p][2], _bq[p][3], b_addr[p] + _bbo + _ko); \
        _Pragma("unroll") for (int mi = 0; mi < 2; mi++) { \
            _Pragma("unroll") for (int p = 0; p < 2; p++) { \
                const uint32_t _b0[2] = {_bq[p][0], _bq[p][1]}; \
                const uint32_t _b1[2] = {_bq[p][2], _bq[p][3]}; \
                mma16816(acc[mi][p * 2 + 0], _af[mi], _b0); \
                mma16816(acc[mi][p * 2 + 1], _af[mi], _b1); \
            } \
        } \
    } \
} while (0)

    // prologue: tile0 -> smem buf0; tile1 -> Ra
    DO_LDG(0, RaA, RaB);
    DO_STS(0, RaA, RaB);
    if (ktiles > 1) DO_LDG(1, RaA, RaB);
    __syncthreads();

    for (int kt = 0; kt < ktiles; kt += 2) {
        // even tile kt: compute buf0; Ra holds kt+1; load kt+2 -> Rb
        if (kt + 2 < ktiles) DO_LDG(kt + 2, RbA, RbB);
        DO_MMA(0);
        if (kt + 1 < ktiles) {
            DO_STS(1, RaA, RaB);
            __syncthreads();
        }
        // odd tile kt+1: compute buf1; Rb holds kt+2; load kt+3 -> Ra
        if (kt + 3 < ktiles) DO_LDG(kt + 3, RaA, RaB);
        if (kt + 1 < ktiles) DO_MMA(1);
        if (kt + 2 < ktiles) {
            DO_STS(0, RbA, RbB);
            __syncthreads();
        }
    }
#undef DO_LDG
#undef DO_STS
#undef DO_MMA
}

#define EPI128_VARS \
    const int lane = threadIdx.x & 31, wid = threadIdx.x >> 5; \
    const int wm = wid & 3, wn = wid >> 2; \
    const int fr = lane >> 2, fc = lane & 3;

// ---- slim path: compute single row (row 256) as fp32 matvec -----------------
__device__ __forceinline__ void slim_row(
    const float* __restrict__ Arow, const float* __restrict__ B,
    int K, int bn, int kbeg, int klen,
    float* xs, float* outvals, int* outcols)
{
    const int tid = threadIdx.x;
    const int wid = tid >> 5, lane = tid & 31;
    const int k4 = klen >> 2;
    for (int i = tid; i < k4; i += 256)
        ((float4*)xs)[i] = ((const float4*)Arow)[i];
    __syncthreads();
#pragma unroll
    for (int cc = 0; cc < 8; cc++) {
        const int col = bn + wid * 8 + cc;
        const float4* wr = (const float4*)(B + (size_t)col * K + kbeg);
        float s = 0.f;
        for (int kb = lane; kb < k4; kb += 32) {
            const float4 w = wr[kb], xv = ((const float4*)xs)[kb];
            s += w.x * xv.x + w.y * xv.y + w.z * xv.z + w.w * xv.w;
        }
        s = warpSum(s);
        outvals[cc] = s;
        outcols[cc] = col;
    }
}

// ---- fused QKV ---------------------------------------------------------------
__global__ __launch_bounds__(256) void gemm_qkv_kernel(
    const float* __restrict__ A,
    const float* __restrict__ Wq_, const float* __restrict__ Wk_, const float* __restrict__ Wv_,
    const float* __restrict__ bq_, const float* __restrict__ bk_, const float* __restrict__ bv_,
    float* __restrict__ Q, float* __restrict__ Ko, float* __restrict__ V,
    int M, int N, int K)
{
    __shared__ uint32_t As[2 * A_U32];
    __shared__ uint32_t Bs[2 * B_U32];
    const int z = blockIdx.z;
    const float* B    = (z == 0) ? Wq_ : (z == 1) ? Wk_ : Wv_;
    const float* bias = (z == 0) ? bq_ : (z == 1) ? bk_ : bv_;
    float* C          = (z == 0) ? Q   : (z == 1) ? Ko  : V;
    const int bn = blockIdx.x * 64;

    if (blockIdx.y == 2) {
        float vals[8]; int cols[8];
        slim_row(A + (size_t)256 * K, B, K, bn, 0, K, (float*)As, vals, cols);
        if ((threadIdx.x & 31) == 0) {
#pragma unroll
            for (int cc = 0; cc < 8; cc++)
                C[(size_t)256 * N + cols[cc]] = vals[cc] + bias[cols[cc]];
        }
        return;
    }

    const int bm = blockIdx.y * 128;
    float acc[2][4][4] = {};
    f16_core128(A, B, K, bm, bn, 0, K / 32, acc, As, Bs);

    EPI128_VARS
#pragma unroll
    for (int mi = 0; mi < 2; mi++)
#pragma unroll
        for (int ni = 0; ni < 4; ni++) {
            const int r = bm + wm * 32 + mi * 16 + fr;
            const int c = bn + wn * 32 + ni * 8 + fc * 2;
            const float bx = bias[c], by = bias[c + 1];
            float2 o0 = {acc[mi][ni][0] + bx, acc[mi][ni][1] + by};
            float2 o1 = {acc[mi][ni][2] + bx, acc[mi][ni][3] + by};
            *(float2*)(C + (size_t)r * N + c) = o0;
            *(float2*)(C + (size_t)(r + 8) * N + c) = o1;
        }
}

// ---- direct GEMM with bias (+relu) -------------------------------------------
__global__ __launch_bounds__(256) void gemm_direct_kernel(
    const float* __restrict__ A, const float* __restrict__ B,
    const float* __restrict__ bias, float* __restrict__ C,
    int M, int N, int K, int relu_flag)
{
    __shared__ uint32_t As[2 * A_U32];
    __shared__ uint32_t Bs[2 * B_U32];
    const int bn = blockIdx.x * 64;

    if (blockIdx.y == 2) {
        float vals[8]; int cols[8];
        slim_row(A + (size_t)256 * K, B, K, bn, 0, K, (float*)As, vals, cols);
        if ((threadIdx.x & 31) == 0) {
#pragma unroll
            for (int cc = 0; cc < 8; cc++) {
                float s = vals[cc] + bias[cols[cc]];
                if (relu_flag) s = fmaxf(s, 0.f);
                C[(size_t)256 * N + cols[cc]] = s;
            }
        }
        return;
    }

    const int bm = blockIdx.y * 128;
    float acc[2][4][4] = {};
    f16_core128(A, B, K, bm, bn, 0, K / 32, acc, As, Bs);

    EPI128_VARS
#pragma unroll
    for (int mi = 0; mi < 2; mi++)
#pragma unroll
        for (int ni = 0; ni < 4; ni++) {
            const int r = bm + wm * 32 + mi * 16 + fr;
            const int c = bn + wn * 32 + ni * 8 + fc * 2;
            const float bx = bias[c], by = bias[c + 1];
            float2 o0 = {acc[mi][ni][0] + bx, acc[mi][ni][1] + by};
            float2 o1 = {acc[mi][ni][2] + bx, acc[mi][ni][3] + by};
            if (relu_flag) {
                o0.x = fmaxf(o0.x, 0.f); o0.y = fmaxf(o0.y, 0.f);
                o1.x = fmaxf(o1.x, 0.f); o1.y = fmaxf(o1.y, 0.f);
            }
            *(float2*)(C + (size_t)r * N + c) = o0;
            *(float2*)(C + (size_t)(r + 8) * N + c) = o1;
        }
}

// ---- split-K GEMM (raw partials) ---------------------------------------------
__global__ __launch_bounds__(256) void gemm_splitk_kernel(
    const float* __restrict__ A, const float* __restrict__ B,
    float* __restrict__ part, int M, int N, int K, int klen)
{
    __shared__ uint32_t As[2 * A_U32];
    __shared__ uint32_t Bs[2 * B_U32];
    const int bn = blockIdx.x * 64;
    const int z = blockIdx.z;
    float* C = part + (size_t)z * M * N;

    if (blockIdx.y == 2) {
        float vals[8]; int cols[8];
        slim_row(A + (size_t)256 * K + z * klen, B, K, bn, z * klen, klen, (float*)As, vals, cols);
        if ((threadIdx.x & 31) == 0) {
#pragma unroll
            for (int cc = 0; cc < 8; cc++)
                C[(size_t)256 * N + cols[cc]] = vals[cc];
        }
        return;
    }

    const int bm = blockIdx.y * 128;
    float acc[2][4][4] = {};
    f16_core128(A, B, K, bm, bn, z * klen, klen / 32, acc, As, Bs);

    EPI128_VARS
#pragma unroll
    for (int mi = 0; mi < 2; mi++)
#pragma unroll
        for (int ni = 0; ni < 4; ni++) {
            const int r = bm + wm * 32 + mi * 16 + fr;
            const int c = bn + wn * 32 + ni * 8 + fc * 2;
            float2 o0 = {acc[mi][ni][0], acc[mi][ni][1]};
            float2 o1 = {acc[mi][ni][2], acc[mi][ni][3]};
            *(float2*)(C + (size_t)r * N + c) = o0;
            *(float2*)(C + (size_t)(r + 8) * N + c) = o1;
        }
}

// ---- fused combine(split-K) + bias + residual + LayerNorm --------------------
__global__ __launch_bounds__(256) void combine_ln_kernel(
    const float* __restrict__ part, int KS,
    const float* __restrict__ bias, const float* __restrict__ res,
    const float* __restrict__ g, const float* __restrict__ b,
    float* __restrict__ out, int M)
{
    const int row = blockIdx.x;
    const int tid = threadIdx.x;
    const int lane = tid & 31, warp = tid >> 5;
    __shared__ float rs[8], rs2[8];
    __shared__ float smv[2];

    float4 s = ((const float4*)(part + (size_t)row * D_DIM))[tid];
    for (int z = 1; z < KS; z++) {
        const float4 t = ((const float4*)(part + ((size_t)z * M + row) * D_DIM))[tid];
        s.x += t.x; s.y += t.y; s.z += t.z; s.w += t.w;
    }
    const float4 b4 = ((const float4*)bias)[tid];
    s.x += b4.x; s.y += b4.y; s.z += b4.z; s.w += b4.w;
    const float4 r4 = ((const float4*)(res + (size_t)row * D_DIM))[tid];
    s.x += r4.x; s.y += r4.y; s.z += r4.z; s.w += r4.w;

    float sum = s.x + s.y + s.z + s.w;
    float sq = s.x * s.x + s.y * s.y + s.z * s.z + s.w * s.w;
    sum = warpSum(sum); sq = warpSum(sq);
    if (lane == 0) { rs[warp] = sum; rs2[warp] = sq; }
    __syncthreads();
    if (warp == 0) {
        float t = (lane < 8) ? rs[lane] : 0.f;
        float t2 = (lane < 8) ? rs2[lane] : 0.f;
        t = warpSum(t); t2 = warpSum(t2);
        if (lane == 0) {
            const float mean = t * (1.0f / D_DIM);
            const float var = t2 * (1.0f / D_DIM) - mean * mean;
            smv[0] = mean;
            smv[1] = rsqrtf(var + 1e-5f);
        }
    }
    __syncthreads();
    const float mean = smv[0], inv = smv[1];
    const float4 g4 = ((const float4*)g)[tid];
    const float4 be4 = ((const float4*)b)[tid];
    float4 o;
    o.x = (s.x - mean) * inv * g4.x + be4.x;
    o.y = (s.y - mean) * inv * g4.y + be4.y;
    o.z = (s.z - mean) * inv * g4.z + be4.z;
    o.w = (s.w - mean) * inv * g4.w + be4.w;
    ((float4*)(out + (size_t)row * D_DIM))[tid] = o;
}

// ============================================================================
// Tensor-core attention: block per (head, 16-query tile), 256 threads.
// ============================================================================
#define QT 16
#define TROWW 36
#define SCW 324

__global__ __launch_bounds__(256) void attn_mma_kernel(
    const float* __restrict__ q, const float* __restrict__ k,
    const float* __restrict__ v, float* __restrict__ o)
{
    const int h = blockIdx.x;
    const int qt = blockIdx.y * QT;
    const int tid = threadIdx.x, lane = tid & 31, warp = tid >> 5;
    const int sub = lane >> 3, r8 = lane & 7;

    __shared__ uint32_t Qh[QT][TROWW];
    __shared__ uint32_t Th[64][TROWW];
    __shared__ uint32_t Ph[QT][TROWW];
    __shared__ float sc[QT][SCW];
    __shared__ float inv_s[QT];

    const int nq = min(QT, S_TOK - qt);
    const uint32_t Qh_b = smem_u32p(&Qh[0][0]);
    const uint32_t Th_b = smem_u32p(&Th[0][0]);
    const uint32_t Ph_b = smem_u32p(&Ph[0][0]);

    {
        const int r = tid >> 4, f = tid & 15;
        float4 val = (r < nq) ? *(const float4*)(q + (size_t)(qt + r) * D_DIM + h * DH + f * 4)
                              : make_float4(0.f, 0.f, 0.f, 0.f);
        Qh[r][f * 2]     = pkh2(val.x, val.y);
        Qh[r][f * 2 + 1] = pkh2(val.z, val.w);
    }
    __syncthreads();

    uint32_t qaf[4][4];
    {
        const uint32_t a_base = Qh_b + (((sub & 1) * 8 + r8) * TROWW + (sub >> 1) * 4) * 4;
#pragma unroll
        for (int kc = 0; kc < 4; kc++)
            ldsm4(qaf[kc][0], qaf[kc][1], qaf[kc][2], qaf[kc][3], a_base + kc * 32);
    }

    const int fr = lane >> 2, fc = lane & 3;

    // phase 1: scores
    for (int j0 = 0; j0 < S_TOK; j0 += 64) {
        const int jn = min(64, S_TOK - j0);
        __syncthreads();
#pragma unroll
        for (int i = 0; i < 4; i++) {
            const int idx = tid + i * 256;
            const int r = idx >> 4, f = idx & 15;
            float4 val = (r < jn) ? *(const float4*)(k + (size_t)(j0 + r) * D_DIM + h * DH + f * 4)
                                  : make_float4(0.f, 0.f, 0.f, 0.f);
            Th[r][f * 2]     = pkh2(val.x, val.y);
            Th[r][f * 2 + 1] = pkh2(val.z, val.w);
        }
        __syncthreads();
        float dacc[4] = {0.f, 0.f, 0.f, 0.f};
        const uint32_t b_base = Th_b + ((warp * 8 + r8) * TROWW + (sub & 1) * 4) * 4;
#pragma unroll
        for (int kc = 0; kc < 4; kc++) {
            uint32_t bf0, bf1;
            ldsm2(bf0, bf1, b_base + kc * 32);
            const uint32_t bf[2] = {bf0, bf1};
            mma16816(dacc, qaf[kc], bf);
        }
        const int cb = j0 + warp * 8 + fc * 2;
        sc[fr][cb]         = dacc[0] * 0.125f;
        sc[fr][cb + 1]     = dacc[1] * 0.125f;
        sc[fr + 8][cb]     = dacc[2] * 0.125f;
        sc[fr + 8][cb + 1] = dacc[3] * 0.125f;
    }
    __syncthreads();

    // phase 2: softmax
#pragma unroll
    for (int ri = 0; ri < 2; ri++) {
        const int r = warp * 2 + ri;
        if (r < nq) {
            float m = -1e30f;
            for (int j = lane; j < S_TOK; j += 32) m = fmaxf(m, sc[r][j]);
            m = warpMax(m);
            float ssum = 0.f;
            for (int j = lane; j < S_TOK; j += 32) {
                const float e = __expf(sc[r][j] - m);
                sc[r][j] = e;
                ssum += e;
            }
            ssum = warpSum(ssum);
            if (lane == 0) inv_s[r] = 1.0f / ssum;
        }
    }

    // phase 3: P @ V
    float oacc[4] = {0.f, 0.f, 0.f, 0.f};
    for (int j0 = 0; j0 < S_TOK; j0 += 64) {
        const int jn = min(64, S_TOK - j0);
        __syncthreads();
#pragma unroll
        for (int i = 0; i < 4; i++) {
            const int idx = tid + i * 256;
            const int r = idx >> 4, f = idx & 15;
            float4 val = (r < jn) ? *(const float4*)(v + (size_t)(j0 + r) * D_DIM + h * DH + f * 4)
                                  : make_float4(0.f, 0.f, 0.f, 0.f);
            Th[r][f * 2]     = pkh2(val.x, val.y);
            Th[r][f * 2 + 1] = pkh2(val.z, val.w);
        }
        {
            const int r = tid >> 4, gp = tid & 15;
            const int jb = j0 + gp * 4;
            const float p0 = (jb + 0 < S_TOK) ? sc[r][jb + 0] : 0.f;
            const float p1 = (jb + 1 < S_TOK) ? sc[r][jb + 1] : 0.f;
            const float p2 = (jb + 2 < S_TOK) ? sc[r][jb + 2] : 0.f;
            const float p3 = (jb + 3 < S_TOK) ? sc[r][jb + 3] : 0.f;
            Ph[r][gp * 2]     = pkh2(p0, p1);
            Ph[r][gp * 2 + 1] = pkh2(p2, p3);
        }
        __syncthreads();
        const uint32_t pa_base = Ph_b + (((sub & 1) * 8 + r8) * TROWW + (sub >> 1) * 4) * 4;
        const uint32_t bt_base = Th_b + (((sub & 1) * 8 + r8) * TROWW) * 4 + warp * 16;
#pragma unroll
        for (int kc = 0; kc < 4; kc++) {
            uint32_t paf[4];
            ldsm4(paf[0], paf[1], paf[2], paf[3], pa_base + kc * 32);
            uint32_t bf0, bf1;
            ldsm2t(bf0, bf1, bt_base + kc * 16 * TROWW * 4);
            const uint32_t bf[2] = {bf0, bf1};
            mma16816(oacc, paf, bf);
        }
    }

    const int d = warp * 8 + fc * 2;
    if (fr < nq) {
        const float iv = inv_s[fr];
        float2 o0 = {oacc[0] * iv, oacc[1] * iv};
        *(float2*)(o + (size_t)(qt + fr) * D_DIM + h * DH + d) = o0;
    }
    if (fr + 8 < nq) {
        const float iv = inv_s[fr + 8];
        float2 o1 = {oacc[2] * iv, oacc[3] * iv};
        *(float2*)(o + (size_t)(qt + fr + 8) * D_DIM + h * DH + d) = o1;
    }
}

// ---------------- matvec (embeddings) ---------------------------------------
__global__ __launch_bounds__(256) void matvec_kernel(
    const float* __restrict__ W, const float* __restrict__ bias,
    const float* __restrict__ x, float* __restrict__ out,
    int N, int K, int act)
{
    __shared__ float xs[OBS_N];
    const int tid = threadIdx.x;
    for (int i = tid; i < K; i += 256) xs[i] = x[i];
    __syncthreads();
    const int warp = tid >> 5, lane = tid & 31;
    const int n = blockIdx.x * 8 + warp;
    if (n >= N) return;
    const float4* wr = reinterpret_cast<const float4*>(W + (size_t)n * K);
    const float4* x4 = reinterpret_cast<const float4*>(xs);
    float s = 0.f;
    const int K4 = K >> 2;
    for (int kb = lane; kb < K4; kb += 32) {
        const float4 w = wr[kb], xv = x4[kb];
        s += w.x * xv.x + w.y * xv.y + w.z * xv.z + w.w * xv.w;
    }
    s = warpSum(s);
    if (lane == 0) {
        s += bias[n];
        if (act == 1) s = fmaxf(s, 0.f);
        else if (act == 2) s = tanhf(s);
        out[n] = s;
    }
}

// ---------------- fused output heads (W_out relu | W_concept tanh) ----------
__global__ __launch_bounds__(256) void heads_kernel(
    const float* __restrict__ W_out, const float* __restrict__ b_out,
    const float* __restrict__ W_con, const float* __restrict__ b_con,
    const float* __restrict__ x, float* __restrict__ out)
{
    __shared__ float xs[D_DIM];
    const int tid = threadIdx.x;
    for (int i = tid; i < D_DIM; i += 256) xs[i] = x[i];
    __syncthreads();
    const int warp = tid >> 5, lane = tid & 31;
    const int n = blockIdx.x * 8 + warp;
    const bool is_out = (n < OUT_N);
    const int nn = is_out ? n : n - OUT_N;
    const float* W = is_out ? W_out : W_con;
    const float4* wr = reinterpret_cast<const float4*>(W + (size_t)nn * D_DIM);
    const float4* x4 = reinterpret_cast<const float4*>(xs);
    float s = 0.f;
#pragma unroll 4
    for (int kb = lane; kb < D_DIM / 4; kb += 32) {
        const float4 w = wr[kb], xv = x4[kb];
        s += w.x * xv.x + w.y * xv.y + w.z * xv.z + w.w * xv.w;
    }
    s = warpSum(s);
    if (lane == 0) {
        if (is_out) out[n] = fmaxf(s + b_out[nn], 0.f);
        else        out[n] = tanhf(s + b_con[nn]);
    }
}

// ---------------- concept embedding (rows 1..256 of x) ---------------------
__global__ __launch_bounds__(256) void cemb_kernel(
    const float* __restrict__ concepts, const float* __restrict__ Wc,
    const float* __restrict__ bc, const float* __restrict__ Wage,
    const float* __restrict__ bage, float* __restrict__ x)
{
    const int i = blockIdx.x;
    const int tid = threadIdx.x;
    __shared__ float cv[CSZ];
    if (tid < CSZ) cv[tid] = concepts[i * CSZ + tid];
    __syncthreads();
    const float agef = (float)i / 256.0f;
    for (int d = tid; d < D_DIM; d += 256) {
        const float4* wr = reinterpret_cast<const float4*>(Wc + (size_t)d * CSZ);
        const float4* c4 = reinterpret_cast<const float4*>(cv);
        float s = 0.f;
#pragma unroll
        for (int t = 0; t < CSZ / 4; t++) {
            const float4 w = wr[t], c = c4[t];
            s += w.x * c.x + w.y * c.y + w.z * c.z + w.w * c.w;
        }
        s += bc[d] + Wage[(size_t)d * AGE_V + i] + agef * Wage[(size_t)d * AGE_V + (AGE_V - 1)] + bage[d];
        x[(size_t)(i + 1) * D_DIM + d] = s;
    }
}

// ---------------- host launch ----------------------------------------------
extern "C" void kernel_launch(void* const* d_in, const int* in_sizes, int n_in,
                              void* d_out, int out_size)
{
    const float* observation = (const float*)d_in[0];
    const float* concepts    = (const float*)d_in[1];
    const float* W_core = (const float*)d_in[2];
    const float* b_core = (const float*)d_in[3];
    const float* W_cemb = (const float*)d_in[4];
    const float* b_cemb = (const float*)d_in[5];
    const float* W_age  = (const float*)d_in[6];
    const float* b_age  = (const float*)d_in[7];
    const float* Wq = (const float*)d_in[8];
    const float* bq = (const float*)d_in[9];
    const float* Wk = (const float*)d_in[10];
    const float* bk = (const float*)d_in[11];
    const float* Wv = (const float*)d_in[12];
    const float* bv = (const float*)d_in[13];
    const float* Wo = (const float*)d_in[14];
    const float* bo = (const float*)d_in[15];
    const float* ln1_g = (const float*)d_in[16];
    const float* ln1_b = (const float*)d_in[17];
    const float* W1 = (const float*)d_in[18];
    const float* b1 = (const float*)d_in[19];
    const float* W2 = (const float*)d_in[20];
    const float* b2 = (const float*)d_in[21];
    const float* ln2_g = (const float*)d_in[22];
    const float* ln2_b = (const float*)d_in[23];
    const float* W_concept = (const float*)d_in[24];
    const float* b_concept = (const float*)d_in[25];
    const float* W_out = (const float*)d_in[26];
    const float* b_out = (const float*)d_in[27];

    float *x, *q, *k, *v, *ao, *ffn, *part;
    cudaGetSymbolAddress((void**)&x, g_x);
    cudaGetSymbolAddress((void**)&q, g_q);
    cudaGetSymbolAddress((void**)&k, g_k);
    cudaGetSymbolAddress((void**)&v, g_v);
    cudaGetSymbolAddress((void**)&ao, g_ao);
    cudaGetSymbolAddress((void**)&ffn, g_ffn);
    cudaGetSymbolAddress((void**)&part, g_part);

    const int M = S_TOK;
    const dim3 blk(256);
    const dim3 grid_qkv(D_DIM / 64, 3, 3);
    const dim3 grid_o(D_DIM / 64, 3, 4);
    const dim3 grid_w1(HID / 64, 3, 1);
    const dim3 grid_w2(D_DIM / 64, 3, 4);
    const dim3 grid_attn(HEADS, (S_TOK + QT - 1) / QT);

    // --- embeddings ---
    matvec_kernel<<<D_DIM / 8, 256>>>(W_core, b_core, observation, x, D_DIM, OBS_N, 0);
    cemb_kernel<<<NC, 256>>>(concepts, W_cemb, b_cemb, W_age, b_age, x);

    // --- transformer layers ---
    for (int l = 0; l < NLAYER; l++) {
        const size_t od  = (size_t)l * D_DIM * D_DIM;
        const size_t ob  = (size_t)l * D_DIM;
        const size_t o1w = (size_t)l * HID * D_DIM;
        const size_t o1b = (size_t)l * HID;

        gemm_qkv_kernel<<<grid_qkv, blk>>>(x, Wq + od, Wk + od, Wv + od,
                                           bq + ob, bk + ob, bv + ob,
                                           q, k, v, M, D_DIM, D_DIM);

        attn_mma_kernel<<<grid_attn, 256>>>(q, k, v, ao);

        gemm_splitk_kernel<<<grid_o, blk>>>(ao, Wo + od, part, M, D_DIM, D_DIM, D_DIM / 4);
        combine_ln_kernel<<<M, 256>>>(part, 4, bo + ob, x, ln1_g + ob, ln1_b + ob, x, M);

        gemm_direct_kernel<<<grid_w1, blk>>>(x, W1 + o1w, b1 + o1b, ffn, M, HID, D_DIM, 1);
        gemm_splitk_kernel<<<grid_w2, blk>>>(ffn, W2 + o1w, part, M, D_DIM, HID, HID / 4);
        combine_ln_kernel<<<M, 256>>>(part, 4, b2 + ob, x, ln2_g + ob, ln2_b + ob, x, M);
    }

    // --- heads (node 0) -> d_out = [output(512) | new_concept(128)] ---
    float* out = (float*)d_out;
    heads_kernel<<<(OUT_N + CSZ) / 8, 256>>>(W_out, b_out, W_concept, b_concept, x, out);

    (void)in_sizes; (void)n_in; (void)out_size;
}